// round 5
// baseline (speedup 1.0000x reference)
#include <cuda_runtime.h>
#include <cuda_bf16.h>

// Problem constants (fixed by the reference)
#define PB 64
#define PT 512
#define PD 1024
#define TS 16                 // T-chunks
#define TT (PT / TS)          // 32 rows per block (== warp size)
#define BLOCKS_PER_B (2 * TS) // 32 blocks cover one b

// Zero-invariant scratch: statically zero-initialized at module load; the
// finalizer block restores zeros after consuming, so every kernel_launch call
// (correctness run + each graph replay) sees zeros.
__device__ float    g_S  [PB * PD];  // unnormalized s[b,d]
__device__ float    g_YH [PB * PD];  // unnormalized y_hat[b,d]
__device__ unsigned g_cnt[PB];       // per-b arrival counters

// ---------------------------------------------------------------------------
// Single fused kernel.
// grid (2, TS, PB), block (128). Each thread owns one float4 d-column of a
// 32-row t-chunk. Fully-masked chunks skip straight to the arrival counter.
// The last-arriving block per b finalizes: L1-norm, y, y_hat, scratch reset.
// ---------------------------------------------------------------------------
__global__ void __launch_bounds__(128)
k_fused(const float* __restrict__ vs,
        const int*   __restrict__ len,
        const int*   __restrict__ word,
        const float* __restrict__ weights,
        float*       __restrict__ out)
{
    const int b  = blockIdx.z;
    const int L  = __ldg(len + b);
    const int t0 = blockIdx.y * TT;

    if (t0 < L) {
        const int n = min(L - t0, TT);

        // Warp-wide weight gather: lane j holds weights[word[b, t0+j]]
        // (indices always in-bounds; values beyond n unused).
        const int   lane  = threadIdx.x & 31;
        const float wlane = weights[word[b * PT + t0 + lane]];

        const int d0 = blockIdx.x * 512 + threadIdx.x * 4;

        const float4* __restrict__ p =
            reinterpret_cast<const float4*>(vs + ((size_t)b * PT + t0) * PD + d0);
        const size_t stride = PD / 4;

        float4 acc  = make_float4(0.f, 0.f, 0.f, 0.f);
        float4 accw = make_float4(0.f, 0.f, 0.f, 0.f);

#pragma unroll 4
        for (int i = 0; i < n; ++i) {
            const float4 v = p[(size_t)i * stride];
            const float  w = __shfl_sync(0xFFFFFFFFu, wlane, i);
            acc.x  += v.x;      acc.y  += v.y;      acc.z  += v.z;      acc.w  += v.w;
            accw.x += w * v.x;  accw.y += w * v.y;  accw.z += w * v.z;  accw.w += w * v.w;
        }

        float* sp = g_S + (size_t)b * PD + d0;
        atomicAdd(sp + 0, acc.x);
        atomicAdd(sp + 1, acc.y);
        atomicAdd(sp + 2, acc.z);
        atomicAdd(sp + 3, acc.w);

        float* yp = g_YH + (size_t)b * PD + d0;
        atomicAdd(yp + 0, accw.x);
        atomicAdd(yp + 1, accw.y);
        atomicAdd(yp + 2, accw.z);
        atomicAdd(yp + 3, accw.w);
    }

    // Arrival: make our atomics globally visible, then take a ticket.
    __threadfence();
    __shared__ unsigned s_ticket;
    if (threadIdx.x == 0)
        s_ticket = atomicAdd(&g_cnt[b], 1u);
    __syncthreads();
    if (s_ticket != BLOCKS_PER_B - 1) return;

    // ---- Finalizer path: all 32 blocks for this b have contributed. ----
    __threadfence();  // acquire side: order our g_S/g_YH reads after the count
    if (threadIdx.x == 0) g_cnt[b] = 0;  // reset for next replay (stream-serialized)

    const int tid = threadIdx.x;
    float4* sB = reinterpret_cast<float4*>(g_S  + (size_t)b * PD);
    float4* hB = reinterpret_cast<float4*>(g_YH + (size_t)b * PD);

    const float4 s0 = sB[tid];
    const float4 s1 = sB[tid + 128];
    const float4 h0 = hB[tid];
    const float4 h1 = hB[tid + 128];

    float part = fabsf(s0.x) + fabsf(s0.y) + fabsf(s0.z) + fabsf(s0.w)
               + fabsf(s1.x) + fabsf(s1.y) + fabsf(s1.z) + fabsf(s1.w);

#pragma unroll
    for (int o = 16; o > 0; o >>= 1)
        part += __shfl_xor_sync(0xFFFFFFFFu, part, o);

    __shared__ float sm[4];
    if ((tid & 31) == 0) sm[tid >> 5] = part;
    __syncthreads();

    float tot = 0.f;
#pragma unroll
    for (int i = 0; i < 4; ++i) tot += sm[i];

    const float r = rsqrtf(tot);

    float4* outY = reinterpret_cast<float4*>(out + (size_t)b * PD);
    float4* outH = reinterpret_cast<float4*>(out + (size_t)(PB + b) * PD);
    outY[tid]       = make_float4(s0.x * r, s0.y * r, s0.z * r, s0.w * r);
    outY[tid + 128] = make_float4(s1.x * r, s1.y * r, s1.z * r, s1.w * r);
    outH[tid]       = h0;
    outH[tid + 128] = h1;

    // restore zero-invariant for the next launch/replay
    const float4 z = make_float4(0.f, 0.f, 0.f, 0.f);
    sB[tid]       = z;
    sB[tid + 128] = z;
    hB[tid]       = z;
    hB[tid + 128] = z;
}

// ---------------------------------------------------------------------------
// Entry point: one kernel, one launch.
// ---------------------------------------------------------------------------
extern "C" void kernel_launch(void* const* d_in, const int* in_sizes, int n_in,
                              void* d_out, int out_size)
{
    const float* vs      = (const float*)d_in[0];  // [B,T,D] f32
    const int*   len     = (const int*)  d_in[1];  // [B]
    const int*   word    = (const int*)  d_in[2];  // [B,T]
    const float* weights = (const float*)d_in[3];  // [VOCAB]

    float* out = (float*)d_out;  // y at [0, B*D), y_hat at [B*D, 2*B*D)

    k_fused<<<dim3(2, TS, PB), 128>>>(vs, len, word, weights, out);
}

// round 6
// speedup vs baseline: 1.0911x; 1.0911x over previous
#include <cuda_runtime.h>
#include <cuda_bf16.h>

// Problem constants (fixed by the reference)
#define PB 64
#define PT 512
#define PD 1024
#define TS 16          // T-chunks
#define TT (PT / TS)   // 32 rows per main block (== warp size)

// Zero-invariant scratch: statically zero-initialized at module load;
// k_norm restores zeros after consuming, so every kernel_launch call
// (correctness run + each graph replay) sees zeros.
__device__ float g_S [PB * PD];   // unnormalized s[b,d]
__device__ float g_YH[PB * PD];   // unnormalized y_hat[b,d]

// ---------------------------------------------------------------------------
// Kernel 1: masked partial sums over a T-chunk, accumulate via atomics.
// grid (2, TS, PB), block (128). Each thread owns one float4 d-column.
// Blocks whose whole t-range is masked exit before any global load.
// ---------------------------------------------------------------------------
__global__ void __launch_bounds__(128)
k_main(const float* __restrict__ vs,
       const int* __restrict__ len,
       const int* __restrict__ word,
       const float* __restrict__ weights)
{
    const int b  = blockIdx.z;
    const int L  = __ldg(len + b);
    const int t0 = blockIdx.y * TT;
    if (t0 >= L) return;                       // fully masked chunk: no traffic
    const int n  = min(L - t0, TT);

    // Warp-wide weight gather: lane j holds weights[word[b, t0+j]]
    // (indices always in-bounds; values beyond n unused).
    const int   lane  = threadIdx.x & 31;
    const float wlane = weights[word[b * PT + t0 + lane]];

    const int d0 = blockIdx.x * 512 + threadIdx.x * 4;

    const float4* __restrict__ p =
        reinterpret_cast<const float4*>(vs + ((size_t)b * PT + t0) * PD + d0);
    const size_t stride = PD / 4;

    float4 acc  = make_float4(0.f, 0.f, 0.f, 0.f);
    float4 accw = make_float4(0.f, 0.f, 0.f, 0.f);

#pragma unroll 4
    for (int i = 0; i < n; ++i) {
        const float4 v = p[(size_t)i * stride];
        const float  w = __shfl_sync(0xFFFFFFFFu, wlane, i);
        acc.x  += v.x;      acc.y  += v.y;      acc.z  += v.z;      acc.w  += v.w;
        accw.x += w * v.x;  accw.y += w * v.y;  accw.z += w * v.z;  accw.w += w * v.w;
    }

    float* sp = g_S + (size_t)b * PD + d0;
    atomicAdd(sp + 0, acc.x);
    atomicAdd(sp + 1, acc.y);
    atomicAdd(sp + 2, acc.z);
    atomicAdd(sp + 3, acc.w);

    float* yp = g_YH + (size_t)b * PD + d0;
    atomicAdd(yp + 0, accw.x);
    atomicAdd(yp + 1, accw.y);
    atomicAdd(yp + 2, accw.z);
    atomicAdd(yp + 3, accw.w);
}

// ---------------------------------------------------------------------------
// Kernel 2 (PDL secondary): per-b L1 norm of s, write y and y_hat, restore
// the zero-invariant. Launched with programmatic stream serialization so its
// launch/ramp overlaps k_main; cudaGridDependencySynchronize() blocks until
// k_main's grid (and all its memory ops) completes.
// grid (PB), block (256); each thread holds one float4 per half-row.
// ---------------------------------------------------------------------------
__global__ void __launch_bounds__(256)
k_norm(float* __restrict__ out)
{
    const int b   = blockIdx.x;
    const int tid = threadIdx.x;

    // Prelude (overlaps the primary kernel)
    float4* sP = reinterpret_cast<float4*>(g_S  + (size_t)b * PD) + tid;
    float4* hP = reinterpret_cast<float4*>(g_YH + (size_t)b * PD) + tid;
    float4* outY = reinterpret_cast<float4*>(out + (size_t)b * PD) + tid;
    float4* outH = reinterpret_cast<float4*>(out + (size_t)(PB + b) * PD) + tid;

    // Wait for k_main completion (full visibility of its atomics)
    cudaGridDependencySynchronize();

    const float4 s4 = *sP;
    const float4 h4 = *hP;

    float part = fabsf(s4.x) + fabsf(s4.y) + fabsf(s4.z) + fabsf(s4.w);

#pragma unroll
    for (int o = 16; o > 0; o >>= 1)
        part += __shfl_xor_sync(0xFFFFFFFFu, part, o);

    __shared__ float sm[8];
    if ((tid & 31) == 0) sm[tid >> 5] = part;
    __syncthreads();

    float tot = 0.f;
#pragma unroll
    for (int i = 0; i < 8; ++i) tot += sm[i];

    const float r = rsqrtf(tot);

    *outY = make_float4(s4.x * r, s4.y * r, s4.z * r, s4.w * r);
    *outH = h4;

    // restore zero-invariant for the next launch/replay
    const float4 z = make_float4(0.f, 0.f, 0.f, 0.f);
    *sP = z;
    *hP = z;
}

// ---------------------------------------------------------------------------
// Entry point
// ---------------------------------------------------------------------------
extern "C" void kernel_launch(void* const* d_in, const int* in_sizes, int n_in,
                              void* d_out, int out_size)
{
    const float* vs      = (const float*)d_in[0];  // [B,T,D] f32
    const int*   len     = (const int*)  d_in[1];  // [B]
    const int*   word    = (const int*)  d_in[2];  // [B,T]
    const float* weights = (const float*)d_in[3];  // [VOCAB]

    float* out = (float*)d_out;  // y at [0, B*D), y_hat at [B*D, 2*B*D)

    k_main<<<dim3(2, TS, PB), 128>>>(vs, len, word, weights);

    // Secondary launch with programmatic stream serialization (PDL):
    // launch overhead overlaps k_main; ordering enforced in-kernel by
    // cudaGridDependencySynchronize().
    cudaLaunchAttribute attr[1];
    attr[0].id = cudaLaunchAttributeProgrammaticStreamSerialization;
    attr[0].val.programmaticStreamSerializationAllowed = 1;

    cudaLaunchConfig_t cfg = {};
    cfg.gridDim  = dim3(PB, 1, 1);
    cfg.blockDim = dim3(256, 1, 1);
    cfg.dynamicSmemBytes = 0;
    cfg.stream = 0;
    cfg.attrs = attr;
    cfg.numAttrs = 1;

    cudaLaunchKernelEx(&cfg, k_norm, out);
}

// round 7
// speedup vs baseline: 1.1099x; 1.0172x over previous
#include <cuda_runtime.h>
#include <cuda_bf16.h>

// Problem constants (fixed by the reference)
#define PB 64
#define PT 512
#define PD 1024
#define TS 16                 // T-chunks
#define TT (PT / TS)          // 32 rows per contributor block (== warp size)
#define NCONTRIB (2 * TS)     // 32 contributor blocks per b

// Zero-invariant scratch: statically zero-initialized at module load; the
// per-b finalizer restores zeros after consuming, so every kernel_launch call
// (correctness run + each graph replay) sees zeros.
__device__ float    g_S  [PB * PD];  // unnormalized s[b,d]
__device__ float    g_YH [PB * PD];  // unnormalized y_hat[b,d]
__device__ unsigned g_cnt[PB];       // per-b arrival counters

// ---------------------------------------------------------------------------
// Single fused kernel. grid (2, TS+1, PB), block 128.
//   by <  TS : contributor — masked partial sums over a 32-row t-chunk,
//              atomicAdd into g_S/g_YH, then ONE release-increment of g_cnt[b]
//              by thread 0 (after __syncthreads; cumulativity covers the
//              whole block's atomics).
//   by == TS, bx == 0 : finalizer for b — acquire-spin until all 32
//              contributors arrived, then L1-norm + outputs + scratch reset.
//              Per-b finalize overlaps other batches' streaming.
// ---------------------------------------------------------------------------
__global__ void __launch_bounds__(128)
k_fused(const float* __restrict__ vs,
        const int*   __restrict__ len,
        const int*   __restrict__ word,
        const float* __restrict__ weights,
        float*       __restrict__ out)
{
    const int b = blockIdx.z;

    if (blockIdx.y == TS) {
        if (blockIdx.x != 0) return;
        // ---------------- finalizer for batch b ----------------
        unsigned* cnt = &g_cnt[b];
        if (threadIdx.x == 0) {
            unsigned v;
            for (;;) {
                asm volatile("ld.acquire.gpu.global.u32 %0, [%1];"
                             : "=r"(v) : "l"(cnt) : "memory");
                if (v >= NCONTRIB) break;
                __nanosleep(64);
            }
            *cnt = 0;  // reset for next replay (kernel-boundary ordering)
        }
        __syncthreads();

        const int tid = threadIdx.x;
        float4* sB = reinterpret_cast<float4*>(g_S  + (size_t)b * PD);
        float4* hB = reinterpret_cast<float4*>(g_YH + (size_t)b * PD);

        float4 s[2], h[2];
#pragma unroll
        for (int j = 0; j < 2; ++j) {
            s[j] = __ldcg(sB + tid + 128 * j);
            h[j] = __ldcg(hB + tid + 128 * j);
        }

        float part = 0.f;
#pragma unroll
        for (int j = 0; j < 2; ++j)
            part += fabsf(s[j].x) + fabsf(s[j].y) + fabsf(s[j].z) + fabsf(s[j].w);

#pragma unroll
        for (int o = 16; o > 0; o >>= 1)
            part += __shfl_xor_sync(0xFFFFFFFFu, part, o);

        __shared__ float sm[4];
        if ((tid & 31) == 0) sm[tid >> 5] = part;
        __syncthreads();
        float tot = sm[0] + sm[1] + sm[2] + sm[3];

        const float r = rsqrtf(tot);

        float4* outY = reinterpret_cast<float4*>(out + (size_t)b * PD);
        float4* outH = reinterpret_cast<float4*>(out + (size_t)(PB + b) * PD);
        const float4 z = make_float4(0.f, 0.f, 0.f, 0.f);
#pragma unroll
        for (int j = 0; j < 2; ++j) {
            outY[tid + 128 * j] =
                make_float4(s[j].x * r, s[j].y * r, s[j].z * r, s[j].w * r);
            outH[tid + 128 * j] = h[j];
            sB[tid + 128 * j] = z;   // restore zero-invariant
            hB[tid + 128 * j] = z;
        }
        return;
    }

    // ---------------- contributor ----------------
    const int L  = __ldg(len + b);
    const int t0 = blockIdx.y * TT;

    if (t0 < L) {
        const int n = min(L - t0, TT);

        // Warp-wide weight gather: lane j holds weights[word[b, t0+j]]
        const int   lane  = threadIdx.x & 31;
        const float wlane = weights[word[b * PT + t0 + lane]];

        const int d0 = blockIdx.x * 512 + threadIdx.x * 4;

        const float4* __restrict__ p =
            reinterpret_cast<const float4*>(vs + ((size_t)b * PT + t0) * PD + d0);
        const size_t stride = PD / 4;

        float4 acc  = make_float4(0.f, 0.f, 0.f, 0.f);
        float4 accw = make_float4(0.f, 0.f, 0.f, 0.f);

#pragma unroll 4
        for (int i = 0; i < n; ++i) {
            const float4 v = p[(size_t)i * stride];
            const float  w = __shfl_sync(0xFFFFFFFFu, wlane, i);
            acc.x  += v.x;      acc.y  += v.y;      acc.z  += v.z;      acc.w  += v.w;
            accw.x += w * v.x;  accw.y += w * v.y;  accw.z += w * v.z;  accw.w += w * v.w;
        }

        float* sp = g_S + (size_t)b * PD + d0;
        atomicAdd(sp + 0, acc.x);
        atomicAdd(sp + 1, acc.y);
        atomicAdd(sp + 2, acc.z);
        atomicAdd(sp + 3, acc.w);

        float* yp = g_YH + (size_t)b * PD + d0;
        atomicAdd(yp + 0, accw.x);
        atomicAdd(yp + 1, accw.y);
        atomicAdd(yp + 2, accw.z);
        atomicAdd(yp + 3, accw.w);
    }

    // Arrival: CTA barrier (happens-before from all threads to thread 0),
    // then a single gpu-scope release increment. Cumulativity makes every
    // thread's atomics visible to the finalizer's acquire.
    __syncthreads();
    if (threadIdx.x == 0) {
        asm volatile("red.release.gpu.global.add.u32 [%0], %1;"
                     :: "l"(&g_cnt[b]), "r"(1u) : "memory");
    }
}

// ---------------------------------------------------------------------------
// Entry point: one kernel, one launch.
// ---------------------------------------------------------------------------
extern "C" void kernel_launch(void* const* d_in, const int* in_sizes, int n_in,
                              void* d_out, int out_size)
{
    const float* vs      = (const float*)d_in[0];  // [B,T,D] f32
    const int*   len     = (const int*)  d_in[1];  // [B]
    const int*   word    = (const int*)  d_in[2];  // [B,T]
    const float* weights = (const float*)d_in[3];  // [VOCAB]

    float* out = (float*)d_out;  // y at [0, B*D), y_hat at [B*D, 2*B*D)

    k_fused<<<dim3(2, TS + 1, PB), 128>>>(vs, len, word, weights, out);
}